// round 11
// baseline (speedup 1.0000x reference)
#include <stdint.h>
#include <cuda_runtime.h>
#include <cuda_bf16.h>
#include <math.h>

// Problem constants
#define D_DIM   256
#define HW      1024
#define N_Q     16384
#define K_CODES 8192
#define Z_ELEMS 4194304

// Output layout (flattened tuple, float32)
#define OFF_LOSS 4194304
#define OFF_IDX  4194305
#define OFF_PLX  4210689

// GEMM tiling: CTA 128q x 256c, 8 warps (2m x 4n), warp tile 64x64
#define QT   128
#define CN   256
#define KC   32          // k per chunk (bf16) = 64B rows
#define NCHUNK 24        // 3 passes x 8 chunks
#define NTH  256

// smem byte offsets
#define SM_EN    0                 // 256 f32 = 1024B
#define SM_ZN    1024              // 128 f32 = 512B
#define SM_DATA  1536              // 3 stages x (A 8KB + B 16KB)
#define STAGE_BYTES 24576
#define SM_TOTAL (1536 + 3 * STAGE_BYTES)   // 75264

// Device scratch
__device__ __nv_bfloat16 g_zh[N_Q * D_DIM];
__device__ __nv_bfloat16 g_zl[N_Q * D_DIM];
__device__ __nv_bfloat16 g_ch[K_CODES * D_DIM];
__device__ __nv_bfloat16 g_cl[K_CODES * D_DIM];
__device__ unsigned long long g_key[N_Q];
__device__ float  g_enorm[K_CODES];
__device__ float  g_znorm[N_Q];
__device__ int    g_bestidx[N_Q];
__device__ int    g_counts[K_CODES];
__device__ double g_mse;

// ---------------------------------------------------------------------------
__device__ __forceinline__ uint32_t smem_u32(const void* p) {
    uint32_t a;
    asm("{ .reg .u64 t; cvta.to.shared.u64 t, %1; cvt.u32.u64 %0, t; }"
        : "=r"(a) : "l"(p));
    return a;
}
__device__ __forceinline__ void cp16s(uint32_t s, const void* g) {
    asm volatile("cp.async.cg.shared.global [%0], [%1], 16;"
                 :: "r"(s), "l"(g) : "memory");
}
#define LDM4(r0, r1, r2, r3, addr) \
    asm volatile("ldmatrix.sync.aligned.m8n8.x4.shared.b16 {%0,%1,%2,%3}, [%4];" \
                 : "=r"(r0), "=r"(r1), "=r"(r2), "=r"(r3) : "r"(addr))
#define MMA(d, a0, a1, a2, a3, b0, b1) \
    asm volatile("mma.sync.aligned.m16n8k16.row.col.f32.bf16.bf16.f32 " \
                 "{%0,%1,%2,%3}, {%4,%5,%6,%7}, {%8,%9}, {%0,%1,%2,%3};" \
                 : "+f"(d[0]), "+f"(d[1]), "+f"(d[2]), "+f"(d[3]) \
                 : "r"(a0), "r"(a1), "r"(a2), "r"(a3), "r"(b0), "r"(b1))

// ---------------------------------------------------------------------------
__global__ void init_kernel() {
    int t = blockIdx.x * blockDim.x + threadIdx.x;
    if (t < K_CODES) g_counts[t] = 0;
    if (t < N_Q)     g_key[t] = 0xFFFFFFFFFFFFFFFFull;
    if (t == 0)      g_mse = 0.0;
}

// z (b,d,hw) -> zh/zl [n][d] bf16 split (transpose via smem tile)
__global__ void split_z_kernel(const float* __restrict__ z) {
    __shared__ float t[32][33];
    int b = blockIdx.z, d0 = blockIdx.y * 32, hw0 = blockIdx.x * 32;
    int x = threadIdx.x, y0 = threadIdx.y;
    for (int y = y0; y < 32; y += 8)
        t[y][x] = z[(size_t)b * 262144 + (size_t)(d0 + y) * HW + hw0 + x];
    __syncthreads();
    for (int y = y0; y < 32; y += 8) {
        float v = t[x][y];
        int n = b * 1024 + hw0 + y;
        __nv_bfloat16 h = __float2bfloat16(v);
        float r = v - __bfloat162float(h);
        g_zh[(size_t)n * D_DIM + d0 + x] = h;
        g_zl[(size_t)n * D_DIM + d0 + x] = __float2bfloat16(r);
    }
}

__global__ void split_cb_kernel(const float* __restrict__ cb) {
    int i = blockIdx.x * 256 + threadIdx.x;
    float v = cb[i];
    __nv_bfloat16 h = __float2bfloat16(v);
    g_ch[i] = h;
    g_cl[i] = __float2bfloat16(v - __bfloat162float(h));
}

// znorm: sequential __fadd_rn(__fmul_rn) mimics reference (zf*zf).sum()
__global__ void znorm_kernel(const float* __restrict__ z) {
    int n = blockIdx.x * blockDim.x + threadIdx.x;
    if (n >= N_Q) return;
    int b = n >> 10, hw = n & 1023;
    const float* p = z + (size_t)b * (D_DIM * HW) + hw;
    float s = 0.f;
#pragma unroll 8
    for (int d = 0; d < D_DIM; d++) {
        float v = p[(size_t)d * HW];
        s = __fadd_rn(s, __fmul_rn(v, v));
    }
    g_znorm[n] = s;
}

__global__ void enorm_kernel(const float* __restrict__ cbk) {
    int code = blockIdx.x * 8 + (threadIdx.x >> 5);
    int lane = threadIdx.x & 31;
    const float* p = cbk + (size_t)code * D_DIM;
    float s = 0.f;
#pragma unroll
    for (int i = 0; i < 8; i++) {
        float v = p[i * 32 + lane];
        s = fmaf(v, v, s);
    }
#pragma unroll
    for (int o = 16; o > 0; o >>= 1)
        s += __shfl_xor_sync(0xffffffffu, s, o);
    if (lane == 0) g_enorm[code] = s;
}

// ---------------------------------------------------------------------------
// Main kernel: mma.sync bf16 double-split distance GEMM + fused argmin.
// CTA = 128 queries x 256 codes; effective K = 768 (zh*ch, zh*cl, zl*ch).
__global__ __launch_bounds__(NTH, 1)
void mma_argmin_kernel() {
    extern __shared__ __align__(128) char smem[];
    uint32_t sb = smem_u32(smem);
    float* s_en = (float*)(smem + SM_EN);
    float* s_zn = (float*)(smem + SM_ZN);

    const int tid  = threadIdx.x;
    const int lane = tid & 31;
    const int warp = tid >> 5;
    const int wm = (warp >> 2) * 64;     // warp M offset (0 or 64)
    const int wn = (warp & 3) * 64;      // warp N offset
    const int c0 = blockIdx.x * CN;
    const int q0 = blockIdx.y * QT;

    if (tid < CN) s_en[tid] = g_enorm[c0 + tid];
    if (tid < QT) s_zn[tid] = g_znorm[q0 + tid];

    float acc[4][8][4];
#pragma unroll
    for (int i = 0; i < 4; i++)
#pragma unroll
        for (int j = 0; j < 8; j++)
#pragma unroll
            for (int e = 0; e < 4; e++) acc[i][j][e] = 0.f;

    // ldmatrix address precompute
    // A x4 for m-tile i: lanes l: matrix m=l>>3; rows wm+i*16+(m&1)*8+(l&7); khalf=m>>1
    int am   = lane >> 3;
    int rA[4], xA[4];
#pragma unroll
    for (int i = 0; i < 4; i++) {
        int row = wm + i * 16 + (am & 1) * 8 + (lane & 7);
        rA[i] = row * 64;
        xA[i] = (row >> 1) & 3;
    }
    int akh = am >> 1;                   // k-half from matrix id
    // B x4 for n-pair p: rows wn+(2p + (l>>4))*8 + (l&7); khalf=(l>>3)&1
    int rB[4], xB[4];
#pragma unroll
    for (int p = 0; p < 4; p++) {
        int row = wn + (2 * p + (lane >> 4)) * 8 + (lane & 7);
        rB[p] = row * 64;
        xB[p] = (row >> 1) & 3;
    }
    int bkh = (lane >> 3) & 1;

    // stage loader: chunk it -> buffer it%3
    auto load_chunk = [&](int it) {
        int p = it >> 3, kb = it & 7, buf = it % 3;
        const __nv_bfloat16* Asrc = (p < 2) ? g_zh : g_zl;
        const __nv_bfloat16* Bsrc = (p == 1) ? g_cl : g_ch;
        uint32_t Ab = sb + SM_DATA + buf * STAGE_BYTES;
        uint32_t Bb = Ab + 8192;
#pragma unroll
        for (int q = 0; q < 2; q++) {
            int lin = tid + q * NTH, row = lin >> 2, c16 = lin & 3;
            cp16s(Ab + row * 64 + (((c16 ^ ((row >> 1) & 3)) << 4)),
                  Asrc + (size_t)(q0 + row) * D_DIM + kb * KC + c16 * 8);
        }
#pragma unroll
        for (int q = 0; q < 4; q++) {
            int lin = tid + q * NTH, row = lin >> 2, c16 = lin & 3;
            cp16s(Bb + row * 64 + (((c16 ^ ((row >> 1) & 3)) << 4)),
                  Bsrc + (size_t)(c0 + row) * D_DIM + kb * KC + c16 * 8);
        }
        asm volatile("cp.async.commit_group;" ::: "memory");
    };

    load_chunk(0);
    load_chunk(1);

    for (int it = 0; it < NCHUNK; it++) {
        asm volatile("cp.async.wait_group 1;" ::: "memory");
        __syncthreads();
        if (it + 2 < NCHUNK) load_chunk(it + 2);

        uint32_t Ab = sb + SM_DATA + (it % 3) * STAGE_BYTES;
        uint32_t Bb = Ab + 8192;

#pragma unroll
        for (int s = 0; s < 2; s++) {
            uint32_t a[4][4], b[4][4];
#pragma unroll
            for (int i = 0; i < 4; i++) {
                uint32_t addr = Ab + rA[i] + ((((2 * s + akh) ^ xA[i])) << 4);
                LDM4(a[i][0], a[i][1], a[i][2], a[i][3], addr);
            }
#pragma unroll
            for (int p = 0; p < 4; p++) {
                uint32_t addr = Bb + rB[p] + ((((2 * s + bkh) ^ xB[p])) << 4);
                LDM4(b[p][0], b[p][1], b[p][2], b[p][3], addr);
            }
#pragma unroll
            for (int i = 0; i < 4; i++)
#pragma unroll
                for (int j = 0; j < 8; j++)
                    MMA(acc[i][j], a[i][0], a[i][1], a[i][2], a[i][3],
                        b[j >> 1][(j & 1) * 2], b[j >> 1][(j & 1) * 2 + 1]);
        }
    }

    // ---- epilogue: reference-rounded distance + argmin ----
    // acc[i][j]: rows wm+i*16+(lane>>2) (+8 for regs 2,3), cols wn+j*8+(lane&3)*2 (+1)
    unsigned long long* scratch = (unsigned long long*)(smem + SM_DATA); // 4KB
#pragma unroll
    for (int i = 0; i < 4; i++) {
#pragma unroll
        for (int h = 0; h < 2; h++) {
            int rloc = wm + i * 16 + h * 8 + (lane >> 2);
            float zn = s_zn[rloc];
            unsigned long long best = 0xFFFFFFFFFFFFFFFFull;
#pragma unroll
            for (int j = 0; j < 8; j++) {
#pragma unroll
                for (int e = 0; e < 2; e++) {
                    int col = wn + j * 8 + (lane & 3) * 2 + e;
                    float dot = acc[i][j][h * 2 + e];
                    float dist = __fsub_rn(__fadd_rn(zn, s_en[col]),
                                           __fmul_rn(2.0f, dot));
                    unsigned long long key =
                        ((unsigned long long)__float_as_uint(dist) << 32) |
                        (unsigned)(c0 + col);
                    if (key < best) best = key;
                }
            }
            // reduce over the 4 lanes of the quad (cols)
            unsigned long long o1 = __shfl_xor_sync(0xffffffffu, best, 1);
            if (o1 < best) best = o1;
            unsigned long long o2 = __shfl_xor_sync(0xffffffffu, best, 2);
            if (o2 < best) best = o2;
            if ((lane & 3) == 0) scratch[rloc * 4 + (warp & 3)] = best;
        }
    }
    __syncthreads();
    if (tid < QT) {
        unsigned long long best = scratch[tid * 4];
#pragma unroll
        for (int c = 1; c < 4; c++) {
            unsigned long long v = scratch[tid * 4 + c];
            if (v < best) best = v;
        }
        atomicMin(&g_key[q0 + tid], best);
    }
}

// ---------------------------------------------------------------------------
__global__ void decode_kernel(float* __restrict__ out) {
    int n = blockIdx.x * 256 + threadIdx.x;
    unsigned long long key = g_key[n];
    int idx = (int)(unsigned)(key & 0xFFFFFFFFull);
    g_bestidx[n] = idx;
    out[OFF_IDX + n] = (float)idx;
    atomicAdd(&g_counts[idx], 1);
}

__global__ void gather_kernel(const float* __restrict__ z,
                              const float* __restrict__ cbk,
                              float* __restrict__ out) {
    int o  = blockIdx.x * 256 + threadIdx.x;
    int hw = o & 1023;
    int d  = (o >> 10) & 255;
    int b  = o >> 18;
    int n  = (b << 10) + hw;
    int idx = g_bestidx[n];
    float q = cbk[(size_t)idx * D_DIM + d];
    out[o] = q;
    float diff = q - z[o];
    float sq = diff * diff;

    __shared__ float red[256];
    red[threadIdx.x] = sq;
    __syncthreads();
#pragma unroll
    for (int s = 128; s > 0; s >>= 1) {
        if (threadIdx.x < s) red[threadIdx.x] += red[threadIdx.x + s];
        __syncthreads();
    }
    if (threadIdx.x == 0) atomicAdd(&g_mse, (double)red[0]);
}

__global__ void finalize_kernel(float* __restrict__ out) {
    __shared__ double red[256];
    int t = threadIdx.x;
    double s = 0.0;
    for (int i = t; i < K_CODES; i += 256) {
        double p = (double)g_counts[i] * (1.0 / 16384.0);
        s += p * log(p + 1e-10);
    }
    red[t] = s;
    __syncthreads();
#pragma unroll
    for (int st = 128; st > 0; st >>= 1) {
        if (t < st) red[t] += red[t + st];
        __syncthreads();
    }
    if (t == 0) {
        double mse = g_mse / (double)Z_ELEMS;
        out[OFF_LOSS] = (float)(1.25 * mse);
        out[OFF_PLX]  = (float)exp(-red[0]);
    }
}

// ---------------------------------------------------------------------------
extern "C" void kernel_launch(void* const* d_in, const int* in_sizes, int n_in,
                              void* d_out, int out_size) {
    const float* z   = (const float*)d_in[0];
    const float* cbk = (const float*)d_in[1];
    float* out = (float*)d_out;

    cudaFuncSetAttribute(mma_argmin_kernel,
                         cudaFuncAttributeMaxDynamicSharedMemorySize,
                         SM_TOTAL);

    init_kernel<<<N_Q / 256, 256>>>();
    split_z_kernel<<<dim3(HW / 32, D_DIM / 32, 16), dim3(32, 8)>>>(z);
    split_cb_kernel<<<K_CODES * D_DIM / 256, 256>>>(cbk);
    znorm_kernel<<<N_Q / 256, 256>>>(z);
    enorm_kernel<<<K_CODES / 8, 256>>>(cbk);
    mma_argmin_kernel<<<dim3(K_CODES / CN, N_Q / QT), NTH, SM_TOTAL>>>();
    decode_kernel<<<N_Q / 256, 256>>>(out);
    gather_kernel<<<Z_ELEMS / 256, 256>>>(z, cbk, out);
    finalize_kernel<<<1, 256>>>(out);
}

// round 12
// speedup vs baseline: 2.1085x; 2.1085x over previous
#include <stdint.h>
#include <cuda_runtime.h>
#include <cuda_bf16.h>
#include <math.h>

// Problem constants
#define D_DIM   256
#define HW      1024
#define N_Q     16384
#define K_CODES 8192
#define Z_ELEMS 4194304

// Output layout (flattened tuple, float32)
#define OFF_LOSS 4194304
#define OFF_IDX  4194305
#define OFF_PLX  4210689

// GEMM tiling: CTA 128q x 256c, 8 warps (2m x 4n), warp tile 64x64
#define QT   128
#define CN   256
#define KC   32          // k per chunk
#define NKB  8           // K chunks (8 x 32 = 256)
#define NTH  256

// Blocked tile sizes (bytes)
#define A_TILE 8192      // 128 x 32 bf16
#define B_TILE 16384     // 256 x 32 bf16
#define STAGE_BYTES 49152   // A(zh,zl) 16KB + B(ch,cl) 32KB

// smem byte offsets
#define SM_EN    0                 // 256 f32
#define SM_ZN    1024              // 128 f32
#define SM_MBAR  1536              // 2 x 8B
#define SM_DATA  2048              // 2 stages x 48KB
#define SM_TOTAL (2048 + 2 * STAGE_BYTES)   // 100352

// Device scratch: tile-blocked, pre-swizzled bf16 operands
__device__ __align__(1024) char g_Ablk[(size_t)(N_Q / QT) * NKB * 2 * A_TILE];   // 16MB
__device__ __align__(1024) char g_Bblk[(size_t)(K_CODES / CN) * NKB * 2 * B_TILE]; // 8MB
__device__ unsigned long long g_key[N_Q];
__device__ float  g_enorm[K_CODES];
__device__ float  g_znorm[N_Q];
__device__ int    g_bestidx[N_Q];
__device__ int    g_counts[K_CODES];
__device__ double g_mse;

// ---------------------------------------------------------------------------
__device__ __forceinline__ uint32_t smem_u32(const void* p) {
    uint32_t a;
    asm("{ .reg .u64 t; cvta.to.shared.u64 t, %1; cvt.u32.u64 %0, t; }"
        : "=r"(a) : "l"(p));
    return a;
}
__device__ __forceinline__ void mbar_init(uint32_t a, uint32_t cnt) {
    asm volatile("mbarrier.init.shared.b64 [%0], %1;" :: "r"(a), "r"(cnt) : "memory");
}
__device__ __forceinline__ void mbar_expect_tx(uint32_t a, uint32_t tx) {
    asm volatile("mbarrier.arrive.expect_tx.shared.b64 _, [%0], %1;"
                 :: "r"(a), "r"(tx) : "memory");
}
__device__ __forceinline__ void bulk_g2s(uint32_t dst, const void* src,
                                         uint32_t bytes, uint32_t mbar) {
    asm volatile(
        "cp.async.bulk.shared::cluster.global.mbarrier::complete_tx::bytes "
        "[%0], [%1], %2, [%3];"
        :: "r"(dst), "l"(src), "r"(bytes), "r"(mbar) : "memory");
}
__device__ __forceinline__ void mbar_wait(uint32_t a, uint32_t parity) {
    asm volatile(
        "{\n\t.reg .pred P;\n\t"
        "WL%=:\n\t"
        "mbarrier.try_wait.parity.acquire.cta.shared::cta.b64 P, [%0], %1, 0x989680;\n\t"
        "@P bra WD%=;\n\t"
        "bra WL%=;\n\t"
        "WD%=:\n\t}"
        :: "r"(a), "r"(parity) : "memory");
}
#define LDM4(r0, r1, r2, r3, addr) \
    asm volatile("ldmatrix.sync.aligned.m8n8.x4.shared.b16 {%0,%1,%2,%3}, [%4];" \
                 : "=r"(r0), "=r"(r1), "=r"(r2), "=r"(r3) : "r"(addr))
#define MMA(d, a0, a1, a2, a3, b0, b1) \
    asm volatile("mma.sync.aligned.m16n8k16.row.col.f32.bf16.bf16.f32 " \
                 "{%0,%1,%2,%3}, {%4,%5,%6,%7}, {%8,%9}, {%0,%1,%2,%3};" \
                 : "+f"(d[0]), "+f"(d[1]), "+f"(d[2]), "+f"(d[3]) \
                 : "r"(a0), "r"(a1), "r"(a2), "r"(a3), "r"(b0), "r"(b1))

// ---------------------------------------------------------------------------
__global__ void init_kernel() {
    int t = blockIdx.x * blockDim.x + threadIdx.x;
    if (t < K_CODES) g_counts[t] = 0;
    if (t < N_Q)     g_key[t] = 0xFFFFFFFFFFFFFFFFull;
    if (t == 0)      g_mse = 0.0;
}

// z (b,d,hw) -> blocked pre-swizzled A tiles (zh/zl split)
__global__ void pack_z_kernel(const float* __restrict__ z) {
    __shared__ float t[32][33];
    int b = blockIdx.z, d0 = blockIdx.y * 32, hw0 = blockIdx.x * 32;
    int x = threadIdx.x, y0 = threadIdx.y;
    for (int y = y0; y < 32; y += 8)
        t[y][x] = z[(size_t)b * 262144 + (size_t)(d0 + y) * HW + hw0 + x];
    __syncthreads();
    for (int y = y0; y < 32; y += 8) {
        float v = t[x][y];
        int n = b * 1024 + hw0 + y;
        int d = d0 + x;
        __nv_bfloat16 h = __float2bfloat16(v);
        __nv_bfloat16 l = __float2bfloat16(v - __bfloat162float(h));
        int qt = n >> 7, r = n & 127, kb = d >> 5, c = d & 31;
        size_t base = (size_t)((qt * NKB + kb) * 2) * A_TILE
                    + r * 64 + (((c >> 3) ^ ((r >> 1) & 3)) << 4) + (c & 7) * 2;
        *(__nv_bfloat16*)(g_Ablk + base) = h;
        *(__nv_bfloat16*)(g_Ablk + base + A_TILE) = l;
    }
}

// codebook -> blocked pre-swizzled B tiles (ch/cl split)
__global__ void pack_cb_kernel(const float* __restrict__ cb) {
    int i = blockIdx.x * 256 + threadIdx.x;
    int k = i >> 8, d = i & 255;
    float v = cb[i];
    __nv_bfloat16 h = __float2bfloat16(v);
    __nv_bfloat16 l = __float2bfloat16(v - __bfloat162float(h));
    int ct = k >> 8, r = k & 255, kb = d >> 5, c = d & 31;
    size_t base = (size_t)((ct * NKB + kb) * 2) * B_TILE
                + r * 64 + (((c >> 3) ^ ((r >> 1) & 3)) << 4) + (c & 7) * 2;
    *(__nv_bfloat16*)(g_Bblk + base) = h;
    *(__nv_bfloat16*)(g_Bblk + base + B_TILE) = l;
}

// znorm: sequential __fadd_rn(__fmul_rn) — DO NOT change (index stability)
__global__ void znorm_kernel(const float* __restrict__ z) {
    int n = blockIdx.x * blockDim.x + threadIdx.x;
    if (n >= N_Q) return;
    int b = n >> 10, hw = n & 1023;
    const float* p = z + (size_t)b * (D_DIM * HW) + hw;
    float s = 0.f;
#pragma unroll 8
    for (int d = 0; d < D_DIM; d++) {
        float v = p[(size_t)d * HW];
        s = __fadd_rn(s, __fmul_rn(v, v));
    }
    g_znorm[n] = s;
}

__global__ void enorm_kernel(const float* __restrict__ cbk) {
    int code = blockIdx.x * 8 + (threadIdx.x >> 5);
    int lane = threadIdx.x & 31;
    const float* p = cbk + (size_t)code * D_DIM;
    float s = 0.f;
#pragma unroll
    for (int i = 0; i < 8; i++) {
        float v = p[i * 32 + lane];
        s = fmaf(v, v, s);
    }
#pragma unroll
    for (int o = 16; o > 0; o >>= 1)
        s += __shfl_xor_sync(0xffffffffu, s, o);
    if (lane == 0) g_enorm[code] = s;
}

// ---------------------------------------------------------------------------
// Main kernel: bulk-copy-fed mma.sync bf16 double-split GEMM + fused argmin.
// Per k-chunk: 3 combos (zh*ch, zh*cl, zl*ch) accumulated in fp32.
__global__ __launch_bounds__(NTH, 1)
void mma_argmin_kernel() {
    extern __shared__ __align__(1024) char smem[];
    uint32_t sb = smem_u32(smem);
    float* s_en = (float*)(smem + SM_EN);
    float* s_zn = (float*)(smem + SM_ZN);

    const int tid  = threadIdx.x;
    const int lane = tid & 31;
    const int warp = tid >> 5;
    const int wm = (warp >> 2) * 64;
    const int wn = (warp & 3) * 64;
    const int ct = blockIdx.x;           // code tile (32)
    const int qt = blockIdx.y;           // query tile (128)
    const int c0 = ct * CN;
    const int q0 = qt * QT;

    if (tid == 0) {
        mbar_init(sb + SM_MBAR + 0, 1);
        mbar_init(sb + SM_MBAR + 8, 1);
    }
    if (tid < CN) s_en[tid] = g_enorm[c0 + tid];
    if (tid < QT) s_zn[tid] = g_znorm[q0 + tid];
    __syncthreads();

    // stage issue: chunk kb -> buffer kb&1 (one 16KB A-pair + one 32KB B-pair)
    auto issue = [&](int kb) {
        int s = kb & 1;
        uint32_t mb = sb + SM_MBAR + s * 8;
        uint32_t dst = sb + SM_DATA + s * STAGE_BYTES;
        mbar_expect_tx(mb, STAGE_BYTES);
        bulk_g2s(dst, g_Ablk + (size_t)((qt * NKB + kb) * 2) * A_TILE,
                 2 * A_TILE, mb);
        bulk_g2s(dst + 2 * A_TILE, g_Bblk + (size_t)((ct * NKB + kb) * 2) * B_TILE,
                 2 * B_TILE, mb);
    };
    if (tid == 0) { issue(0); issue(1); }

    float acc[4][8][4];
#pragma unroll
    for (int i = 0; i < 4; i++)
#pragma unroll
        for (int j = 0; j < 8; j++)
#pragma unroll
            for (int e = 0; e < 4; e++) acc[i][j][e] = 0.f;

    // ldmatrix address precompute (same mapping as validated R11 kernel)
    int am = lane >> 3;
    int rA[4], xA[4];
#pragma unroll
    for (int i = 0; i < 4; i++) {
        int row = wm + i * 16 + (am & 1) * 8 + (lane & 7);
        rA[i] = row * 64;
        xA[i] = (row >> 1) & 3;
    }
    int akh = am >> 1;
    int rB[4], xB[4];
#pragma unroll
    for (int p = 0; p < 4; p++) {
        int row = wn + (2 * p + (lane >> 4)) * 8 + (lane & 7);
        rB[p] = row * 64;
        xB[p] = (row >> 1) & 3;
    }
    int bkh = (lane >> 3) & 1;

    for (int kb = 0; kb < NKB; kb++) {
        int s = kb & 1;
        mbar_wait(sb + SM_MBAR + s * 8, (kb >> 1) & 1);

        uint32_t stg = sb + SM_DATA + s * STAGE_BYTES;
        uint32_t Abase[3] = {stg, stg, stg + A_TILE};                 // zh, zh, zl
        uint32_t Bbase[3] = {stg + 2 * A_TILE, stg + 2 * A_TILE + B_TILE,
                             stg + 2 * A_TILE};                       // ch, cl, ch

#pragma unroll
        for (int cmb = 0; cmb < 3; cmb++) {
            uint32_t Ab = Abase[cmb], Bb = Bbase[cmb];
#pragma unroll
            for (int st = 0; st < 2; st++) {
                uint32_t a[4][4], b[4][4];
#pragma unroll
                for (int i = 0; i < 4; i++) {
                    uint32_t addr = Ab + rA[i] + (((2 * st + akh) ^ xA[i]) << 4);
                    LDM4(a[i][0], a[i][1], a[i][2], a[i][3], addr);
                }
#pragma unroll
                for (int p = 0; p < 4; p++) {
                    uint32_t addr = Bb + rB[p] + (((2 * st + bkh) ^ xB[p]) << 4);
                    LDM4(b[p][0], b[p][1], b[p][2], b[p][3], addr);
                }
#pragma unroll
                for (int i = 0; i < 4; i++)
#pragma unroll
                    for (int j = 0; j < 8; j++)
                        MMA(acc[i][j], a[i][0], a[i][1], a[i][2], a[i][3],
                            b[j >> 1][(j & 1) * 2], b[j >> 1][(j & 1) * 2 + 1]);
            }
        }

        __syncthreads();                      // stage fully consumed
        if (tid == 0 && kb + 2 < NKB) issue(kb + 2);
    }

    // ---- epilogue: reference-rounded distance + argmin ----
    unsigned long long* scratch = (unsigned long long*)(smem + SM_DATA); // 4KB
#pragma unroll
    for (int i = 0; i < 4; i++) {
#pragma unroll
        for (int h = 0; h < 2; h++) {
            int rloc = wm + i * 16 + h * 8 + (lane >> 2);
            float zn = s_zn[rloc];
            unsigned long long best = 0xFFFFFFFFFFFFFFFFull;
#pragma unroll
            for (int j = 0; j < 8; j++) {
#pragma unroll
                for (int e = 0; e < 2; e++) {
                    int col = wn + j * 8 + (lane & 3) * 2 + e;
                    float dot = acc[i][j][h * 2 + e];
                    float dist = __fsub_rn(__fadd_rn(zn, s_en[col]),
                                           __fmul_rn(2.0f, dot));
                    unsigned long long key =
                        ((unsigned long long)__float_as_uint(dist) << 32) |
                        (unsigned)(c0 + col);
                    if (key < best) best = key;
                }
            }
            unsigned long long o1 = __shfl_xor_sync(0xffffffffu, best, 1);
            if (o1 < best) best = o1;
            unsigned long long o2 = __shfl_xor_sync(0xffffffffu, best, 2);
            if (o2 < best) best = o2;
            if ((lane & 3) == 0) scratch[rloc * 4 + (warp & 3)] = best;
        }
    }
    __syncthreads();
    if (tid < QT) {
        unsigned long long best = scratch[tid * 4];
#pragma unroll
        for (int c = 1; c < 4; c++) {
            unsigned long long v = scratch[tid * 4 + c];
            if (v < best) best = v;
        }
        atomicMin(&g_key[q0 + tid], best);
    }
}

// ---------------------------------------------------------------------------
__global__ void decode_kernel(float* __restrict__ out) {
    int n = blockIdx.x * 256 + threadIdx.x;
    unsigned long long key = g_key[n];
    int idx = (int)(unsigned)(key & 0xFFFFFFFFull);
    g_bestidx[n] = idx;
    out[OFF_IDX + n] = (float)idx;
    atomicAdd(&g_counts[idx], 1);
}

__global__ void gather_kernel(const float* __restrict__ z,
                              const float* __restrict__ cbk,
                              float* __restrict__ out) {
    int o  = blockIdx.x * 256 + threadIdx.x;
    int hw = o & 1023;
    int d  = (o >> 10) & 255;
    int b  = o >> 18;
    int n  = (b << 10) + hw;
    int idx = g_bestidx[n];
    float q = cbk[(size_t)idx * D_DIM + d];
    out[o] = q;
    float diff = q - z[o];
    float sq = diff * diff;

    __shared__ float red[256];
    red[threadIdx.x] = sq;
    __syncthreads();
#pragma unroll
    for (int s = 128; s > 0; s >>= 1) {
        if (threadIdx.x < s) red[threadIdx.x] += red[threadIdx.x + s];
        __syncthreads();
    }
    if (threadIdx.x == 0) atomicAdd(&g_mse, (double)red[0]);
}

__global__ void finalize_kernel(float* __restrict__ out) {
    __shared__ double red[256];
    int t = threadIdx.x;
    double s = 0.0;
    for (int i = t; i < K_CODES; i += 256) {
        double p = (double)g_counts[i] * (1.0 / 16384.0);
        s += p * log(p + 1e-10);
    }
    red[t] = s;
    __syncthreads();
#pragma unroll
    for (int st = 128; st > 0; st >>= 1) {
        if (t < st) red[t] += red[t + st];
        __syncthreads();
    }
    if (t == 0) {
        double mse = g_mse / (double)Z_ELEMS;
        out[OFF_LOSS] = (float)(1.25 * mse);
        out[OFF_PLX]  = (float)exp(-red[0]);
    }
}

// ---------------------------------------------------------------------------
extern "C" void kernel_launch(void* const* d_in, const int* in_sizes, int n_in,
                              void* d_out, int out_size) {
    const float* z   = (const float*)d_in[0];
    const float* cbk = (const float*)d_in[1];
    float* out = (float*)d_out;

    cudaFuncSetAttribute(mma_argmin_kernel,
                         cudaFuncAttributeMaxDynamicSharedMemorySize,
                         SM_TOTAL);

    init_kernel<<<N_Q / 256, 256>>>();
    pack_z_kernel<<<dim3(HW / 32, D_DIM / 32, 16), dim3(32, 8)>>>(z);
    pack_cb_kernel<<<K_CODES * D_DIM / 256, 256>>>(cbk);
    znorm_kernel<<<N_Q / 256, 256>>>(z);
    enorm_kernel<<<K_CODES / 8, 256>>>(cbk);
    mma_argmin_kernel<<<dim3(K_CODES / CN, N_Q / QT), NTH, SM_TOTAL>>>();
    decode_kernel<<<N_Q / 256, 256>>>(out);
    gather_kernel<<<Z_ELEMS / 256, 256>>>(z, cbk, out);
    finalize_kernel<<<1, 256>>>(out);
}

// round 14
// speedup vs baseline: 2.2257x; 1.0556x over previous
#include <stdint.h>
#include <cuda_runtime.h>
#include <cuda_bf16.h>
#include <math.h>

// Problem constants
#define D_DIM   256
#define HW      1024
#define N_Q     16384
#define K_CODES 8192
#define Z_ELEMS 4194304

// Output layout (flattened tuple, float32)
#define OFF_LOSS 4194304
#define OFF_IDX  4194305
#define OFF_PLX  4210689

// GEMM tiling: CTA 128q x 256c, 8 warps (2m x 4n), warp tile 64x64
#define QT   128
#define CN   256
#define KC   32
#define NKB  8
#define NTH  256

// Blocked tile sizes (bytes)
#define A_TILE 8192      // 128 x 32 bf16
#define B_TILE 16384     // 256 x 32 bf16
#define STAGE_BYTES 49152

// smem byte offsets (main kernel)
#define SM_EN    0
#define SM_ZN    1024
#define SM_MBAR  1536
#define SM_DATA  2048
#define SM_TOTAL (2048 + 2 * STAGE_BYTES)   // 100352

// Device scratch: tile-blocked, pre-swizzled bf16 operands
__device__ __align__(1024) char g_Ablk[(size_t)(N_Q / QT) * NKB * 2 * A_TILE];
__device__ __align__(1024) char g_Bblk[(size_t)(K_CODES / CN) * NKB * 2 * B_TILE];
__device__ unsigned long long g_key[N_Q];
__device__ float  g_enorm[K_CODES];
__device__ float  g_znorm[N_Q];
__device__ int    g_bestidx[N_Q];
__device__ int    g_counts[K_CODES];
__device__ double g_mse;

// ---------------------------------------------------------------------------
__device__ __forceinline__ uint32_t smem_u32(const void* p) {
    uint32_t a;
    asm("{ .reg .u64 t; cvta.to.shared.u64 t, %1; cvt.u32.u64 %0, t; }"
        : "=r"(a) : "l"(p));
    return a;
}
__device__ __forceinline__ void mbar_init(uint32_t a, uint32_t cnt) {
    asm volatile("mbarrier.init.shared.b64 [%0], %1;" :: "r"(a), "r"(cnt) : "memory");
}
__device__ __forceinline__ void mbar_expect_tx(uint32_t a, uint32_t tx) {
    asm volatile("mbarrier.arrive.expect_tx.shared.b64 _, [%0], %1;"
                 :: "r"(a), "r"(tx) : "memory");
}
__device__ __forceinline__ void bulk_g2s(uint32_t dst, const void* src,
                                         uint32_t bytes, uint32_t mbar) {
    asm volatile(
        "cp.async.bulk.shared::cluster.global.mbarrier::complete_tx::bytes "
        "[%0], [%1], %2, [%3];"
        :: "r"(dst), "l"(src), "r"(bytes), "r"(mbar) : "memory");
}
__device__ __forceinline__ void mbar_wait(uint32_t a, uint32_t parity) {
    asm volatile(
        "{\n\t.reg .pred P;\n\t"
        "WL%=:\n\t"
        "mbarrier.try_wait.parity.acquire.cta.shared::cta.b64 P, [%0], %1, 0x989680;\n\t"
        "@P bra WD%=;\n\t"
        "bra WL%=;\n\t"
        "WD%=:\n\t}"
        :: "r"(a), "r"(parity) : "memory");
}
#define LDM4(r0, r1, r2, r3, addr) \
    asm volatile("ldmatrix.sync.aligned.m8n8.x4.shared.b16 {%0,%1,%2,%3}, [%4];" \
                 : "=r"(r0), "=r"(r1), "=r"(r2), "=r"(r3) : "r"(addr))
#define MMA(d, a0, a1, a2, a3, b0, b1) \
    asm volatile("mma.sync.aligned.m16n8k16.row.col.f32.bf16.bf16.f32 " \
                 "{%0,%1,%2,%3}, {%4,%5,%6,%7}, {%8,%9}, {%0,%1,%2,%3};" \
                 : "+f"(d[0]), "+f"(d[1]), "+f"(d[2]), "+f"(d[3]) \
                 : "r"(a0), "r"(a1), "r"(a2), "r"(a3), "r"(b0), "r"(b1))

// ---------------------------------------------------------------------------
// Launch #1: znorm (sequential order — DO NOT change) + all scratch init.
__global__ void znorm_init_kernel(const float* __restrict__ z) {
    int n = blockIdx.x * blockDim.x + threadIdx.x;
    if (n >= N_Q) return;
    g_key[n] = 0xFFFFFFFFFFFFFFFFull;
    if (n < K_CODES) g_counts[n] = 0;
    if (n == 0) g_mse = 0.0;
    int b = n >> 10, hw = n & 1023;
    const float* p = z + (size_t)b * (D_DIM * HW) + hw;
    float s = 0.f;
#pragma unroll 32
    for (int d = 0; d < D_DIM; d++) {
        float v = p[(size_t)d * HW];
        s = __fadd_rn(s, __fmul_rn(v, v));
    }
    g_znorm[n] = s;
}

// Launch #2: codebook pack (blocked pre-swizzled ch/cl) + enorm, warp per code.
// enorm op order identical to the previous enorm_kernel (i*32+lane, fmaf).
__global__ void pack_cb_enorm_kernel(const float* __restrict__ cb) {
    int code = blockIdx.x * 8 + (threadIdx.x >> 5);
    int lane = threadIdx.x & 31;
    const float* p = cb + (size_t)code * D_DIM;
    int ct = code >> 8, r = code & 255;
    float s = 0.f;
#pragma unroll
    for (int i = 0; i < 8; i++) {
        float v = p[i * 32 + lane];
        s = fmaf(v, v, s);
        __nv_bfloat16 h = __float2bfloat16(v);
        __nv_bfloat16 l = __float2bfloat16(v - __bfloat162float(h));
        size_t base = (size_t)((ct * NKB + i) * 2) * B_TILE
                    + r * 64 + (((lane >> 3) ^ ((r >> 1) & 3)) << 4) + (lane & 7) * 2;
        *(__nv_bfloat16*)(g_Bblk + base) = h;
        *(__nv_bfloat16*)(g_Bblk + base + B_TILE) = l;
    }
#pragma unroll
    for (int o = 16; o > 0; o >>= 1)
        s += __shfl_xor_sync(0xffffffffu, s, o);
    if (lane == 0) g_enorm[code] = s;
}

// Launch #3: z pack (blocked pre-swizzled zh/zl) via 32x32 transpose tiles.
__global__ void pack_z_kernel(const float* __restrict__ z) {
    __shared__ float t[32][33];
    int b = blockIdx.z, d0 = blockIdx.y * 32, hw0 = blockIdx.x * 32;
    int x = threadIdx.x, y0 = threadIdx.y;
    for (int y = y0; y < 32; y += 8)
        t[y][x] = z[(size_t)b * 262144 + (size_t)(d0 + y) * HW + hw0 + x];
    __syncthreads();
    for (int y = y0; y < 32; y += 8) {
        float v = t[x][y];
        int n = b * 1024 + hw0 + y;
        int d = d0 + x;
        __nv_bfloat16 h = __float2bfloat16(v);
        __nv_bfloat16 l = __float2bfloat16(v - __bfloat162float(h));
        int qt = n >> 7, r = n & 127, kb = d >> 5, c = d & 31;
        size_t base = (size_t)((qt * NKB + kb) * 2) * A_TILE
                    + r * 64 + (((c >> 3) ^ ((r >> 1) & 3)) << 4) + (c & 7) * 2;
        *(__nv_bfloat16*)(g_Ablk + base) = h;
        *(__nv_bfloat16*)(g_Ablk + base + A_TILE) = l;
    }
}

// ---------------------------------------------------------------------------
// Launch #4 (profiled): bulk-copy-fed mma.sync bf16 double-split GEMM + argmin.
__global__ __launch_bounds__(NTH, 1)
void mma_argmin_kernel() {
    extern __shared__ __align__(1024) char smem[];
    uint32_t sb = smem_u32(smem);
    float* s_en = (float*)(smem + SM_EN);
    float* s_zn = (float*)(smem + SM_ZN);

    const int tid  = threadIdx.x;
    const int lane = tid & 31;
    const int warp = tid >> 5;
    const int wm = (warp >> 2) * 64;
    const int wn = (warp & 3) * 64;
    const int ct = blockIdx.x;
    const int qt = blockIdx.y;
    const int c0 = ct * CN;
    const int q0 = qt * QT;

    if (tid == 0) {
        mbar_init(sb + SM_MBAR + 0, 1);
        mbar_init(sb + SM_MBAR + 8, 1);
    }
    if (tid < CN) s_en[tid] = g_enorm[c0 + tid];
    if (tid < QT) s_zn[tid] = g_znorm[q0 + tid];
    __syncthreads();

    auto issue = [&](int kb) {
        int s = kb & 1;
        uint32_t mb = sb + SM_MBAR + s * 8;
        uint32_t dst = sb + SM_DATA + s * STAGE_BYTES;
        mbar_expect_tx(mb, STAGE_BYTES);
        bulk_g2s(dst, g_Ablk + (size_t)((qt * NKB + kb) * 2) * A_TILE,
                 2 * A_TILE, mb);
        bulk_g2s(dst + 2 * A_TILE, g_Bblk + (size_t)((ct * NKB + kb) * 2) * B_TILE,
                 2 * B_TILE, mb);
    };
    if (tid == 0) { issue(0); issue(1); }

    float acc[4][8][4];
#pragma unroll
    for (int i = 0; i < 4; i++)
#pragma unroll
        for (int j = 0; j < 8; j++)
#pragma unroll
            for (int e = 0; e < 4; e++) acc[i][j][e] = 0.f;

    int am = lane >> 3;
    int rA[4], xA[4];
#pragma unroll
    for (int i = 0; i < 4; i++) {
        int row = wm + i * 16 + (am & 1) * 8 + (lane & 7);
        rA[i] = row * 64;
        xA[i] = (row >> 1) & 3;
    }
    int akh = am >> 1;
    int rB[4], xB[4];
#pragma unroll
    for (int p = 0; p < 4; p++) {
        int row = wn + (2 * p + (lane >> 4)) * 8 + (lane & 7);
        rB[p] = row * 64;
        xB[p] = (row >> 1) & 3;
    }
    int bkh = (lane >> 3) & 1;

    for (int kb = 0; kb < NKB; kb++) {
        int s = kb & 1;
        mbar_wait(sb + SM_MBAR + s * 8, (kb >> 1) & 1);

        uint32_t stg = sb + SM_DATA + s * STAGE_BYTES;
        uint32_t Abase[3] = {stg, stg, stg + A_TILE};
        uint32_t Bbase[3] = {stg + 2 * A_TILE, stg + 2 * A_TILE + B_TILE,
                             stg + 2 * A_TILE};

#pragma unroll
        for (int cmb = 0; cmb < 3; cmb++) {
            uint32_t Ab = Abase[cmb], Bb = Bbase[cmb];
#pragma unroll
            for (int st = 0; st < 2; st++) {
                uint32_t a[4][4], b[4][4];
#pragma unroll
                for (int i = 0; i < 4; i++) {
                    uint32_t addr = Ab + rA[i] + (((2 * st + akh) ^ xA[i]) << 4);
                    LDM4(a[i][0], a[i][1], a[i][2], a[i][3], addr);
                }
#pragma unroll
                for (int p = 0; p < 4; p++) {
                    uint32_t addr = Bb + rB[p] + (((2 * st + bkh) ^ xB[p]) << 4);
                    LDM4(b[p][0], b[p][1], b[p][2], b[p][3], addr);
                }
#pragma unroll
                for (int i = 0; i < 4; i++)
#pragma unroll
                    for (int j = 0; j < 8; j++)
                        MMA(acc[i][j], a[i][0], a[i][1], a[i][2], a[i][3],
                            b[j >> 1][(j & 1) * 2], b[j >> 1][(j & 1) * 2 + 1]);
            }
        }

        __syncthreads();
        if (tid == 0 && kb + 2 < NKB) issue(kb + 2);
    }

    // ---- epilogue: reference-rounded distance + argmin ----
    unsigned long long* scratch = (unsigned long long*)(smem + SM_DATA);
#pragma unroll
    for (int i = 0; i < 4; i++) {
#pragma unroll
        for (int h = 0; h < 2; h++) {
            int rloc = wm + i * 16 + h * 8 + (lane >> 2);
            float zn = s_zn[rloc];
            unsigned long long best = 0xFFFFFFFFFFFFFFFFull;
#pragma unroll
            for (int j = 0; j < 8; j++) {
#pragma unroll
                for (int e = 0; e < 2; e++) {
                    int col = wn + j * 8 + (lane & 3) * 2 + e;
                    float dot = acc[i][j][h * 2 + e];
                    float dist = __fsub_rn(__fadd_rn(zn, s_en[col]),
                                           __fmul_rn(2.0f, dot));
                    unsigned long long key =
                        ((unsigned long long)__float_as_uint(dist) << 32) |
                        (unsigned)(c0 + col);
                    if (key < best) best = key;
                }
            }
            unsigned long long o1 = __shfl_xor_sync(0xffffffffu, best, 1);
            if (o1 < best) best = o1;
            unsigned long long o2 = __shfl_xor_sync(0xffffffffu, best, 2);
            if (o2 < best) best = o2;
            if ((lane & 3) == 0) scratch[rloc * 4 + (warp & 3)] = best;
        }
    }
    __syncthreads();
    if (tid < QT) {
        unsigned long long best = scratch[tid * 4];
#pragma unroll
        for (int c = 1; c < 4; c++) {
            unsigned long long v = scratch[tid * 4 + c];
            if (v < best) best = v;
        }
        atomicMin(&g_key[q0 + tid], best);
    }
}

// ---------------------------------------------------------------------------
// Launch #5
__global__ void decode_kernel(float* __restrict__ out) {
    int n = blockIdx.x * 256 + threadIdx.x;
    unsigned long long key = g_key[n];
    int idx = (int)(unsigned)(key & 0xFFFFFFFFull);
    g_bestidx[n] = idx;
    out[OFF_IDX + n] = (float)idx;
    atomicAdd(&g_counts[idx], 1);
}

// Launch #6: tiled gather — coalesced codebook reads AND output writes.
__global__ void gather_kernel(const float* __restrict__ z,
                              const float* __restrict__ cbk,
                              float* __restrict__ out) {
    __shared__ float t[32][33];
    __shared__ int   sidx[32];
    __shared__ float red[256];
    int b = blockIdx.z, d0 = blockIdx.y * 32, hw0 = blockIdx.x * 32;
    int x = threadIdx.x, y0 = threadIdx.y;
    int tid = y0 * 32 + x;

    if (tid < 32) sidx[tid] = g_bestidx[b * 1024 + hw0 + tid];
    __syncthreads();

    // read: row hw -> codebook[idx(hw)][d0..d0+31], 128B coalesced
    for (int hw = y0; hw < 32; hw += 8)
        t[hw][x] = cbk[(size_t)sidx[hw] * D_DIM + d0 + x];
    __syncthreads();

    // write: out[b][d0+dy][hw0+x], 128B coalesced; accumulate mse
    float mse = 0.f;
    for (int dy = y0; dy < 32; dy += 8) {
        size_t o = (size_t)b * 262144 + (size_t)(d0 + dy) * HW + hw0 + x;
        float q = t[x][dy];
        out[o] = q;
        float diff = q - z[o];
        mse = fmaf(diff, diff, mse);
    }
    red[tid] = mse;
    __syncthreads();
#pragma unroll
    for (int s = 128; s > 0; s >>= 1) {
        if (tid < s) red[tid] += red[tid + s];
        __syncthreads();
    }
    if (tid == 0) atomicAdd(&g_mse, (double)red[0]);
}

// Launch #7
__global__ void finalize_kernel(float* __restrict__ out) {
    __shared__ double red[256];
    int t = threadIdx.x;
    double s = 0.0;
    for (int i = t; i < K_CODES; i += 256) {
        double p = (double)g_counts[i] * (1.0 / 16384.0);
        s += p * log(p + 1e-10);
    }
    red[t] = s;
    __syncthreads();
#pragma unroll
    for (int st = 128; st > 0; st >>= 1) {
        if (t < st) red[t] += red[t + st];
        __syncthreads();
    }
    if (t == 0) {
        double mse = g_mse / (double)Z_ELEMS;
        out[OFF_LOSS] = (float)(1.25 * mse);
        out[OFF_PLX]  = (float)exp(-red[0]);
    }
}

// ---------------------------------------------------------------------------
extern "C" void kernel_launch(void* const* d_in, const int* in_sizes, int n_in,
                              void* d_out, int out_size) {
    const float* z   = (const float*)d_in[0];
    const float* cbk = (const float*)d_in[1];
    float* out = (float*)d_out;

    cudaFuncSetAttribute(mma_argmin_kernel,
                         cudaFuncAttributeMaxDynamicSharedMemorySize,
                         SM_TOTAL);

    znorm_init_kernel<<<N_Q / 256, 256>>>(z);                              // 1
    pack_cb_enorm_kernel<<<K_CODES / 8, 256>>>(cbk);                       // 2
    pack_z_kernel<<<dim3(HW / 32, D_DIM / 32, 16), dim3(32, 8)>>>(z);      // 3
    mma_argmin_kernel<<<dim3(K_CODES / CN, N_Q / QT), NTH, SM_TOTAL>>>();  // 4
    decode_kernel<<<N_Q / 256, 256>>>(out);                                // 5
    gather_kernel<<<dim3(HW / 32, D_DIM / 32, 16), dim3(32, 8)>>>(z, cbk, out); // 6
    finalize_kernel<<<1, 256>>>(out);                                      // 7
}